// round 13
// baseline (speedup 1.0000x reference)
#include <cuda_runtime.h>
#include <cuda_bf16.h>
#include <cstdint>

#define NT  4096
#define DM  640
#define NH  10
#define DKH 64
#define HS  (NT * DKH)

// Scratch (allocation-free rule: __device__ globals). Q/K/V stored bf16.
__device__ __nv_bfloat16 g_Q[NT * DM];
__device__ __nv_bfloat16 g_K[NT * DM];
__device__ __nv_bfloat16 g_V[NT * DM];
__device__ float g_AO[NT * DM];

// ---------------------------------------------------------------------------
// Helpers (arch-neutral PTX: sm_80-era, accepted by target sm_103)
// ---------------------------------------------------------------------------
__device__ __forceinline__ uint32_t su32(const void* p) {
    uint32_t a;
    asm("{ .reg .u64 t; cvta.to.shared.u64 t, %1; cvt.u32.u64 %0, t; }"
        : "=r"(a) : "l"(p));
    return a;
}
// pack two f32 -> bf16x2 (lo = first arg)
__device__ __forceinline__ uint32_t packbf(float lo, float hi) {
    uint32_t r;
    asm("cvt.rn.bf16x2.f32 %0, %1, %2;" : "=r"(r) : "f"(hi), "f"(lo));
    return r;
}
__device__ __forceinline__ void ldsm4(uint32_t r[4], uint32_t a) {
    asm volatile("ldmatrix.sync.aligned.m8n8.x4.shared.b16 {%0,%1,%2,%3}, [%4];"
        : "=r"(r[0]), "=r"(r[1]), "=r"(r[2]), "=r"(r[3]) : "r"(a));
}
__device__ __forceinline__ void ldsm4t(uint32_t r[4], uint32_t a) {
    asm volatile("ldmatrix.sync.aligned.m8n8.x4.trans.shared.b16 {%0,%1,%2,%3}, [%4];"
        : "=r"(r[0]), "=r"(r[1]), "=r"(r[2]), "=r"(r[3]) : "r"(a));
}
__device__ __forceinline__ void mma16816(float* c, const uint32_t* a,
                                         uint32_t b0, uint32_t b1) {
    asm volatile("mma.sync.aligned.m16n8k16.row.col.f32.bf16.bf16.f32 "
        "{%0,%1,%2,%3}, {%4,%5,%6,%7}, {%8,%9}, {%0,%1,%2,%3};"
        : "+f"(c[0]), "+f"(c[1]), "+f"(c[2]), "+f"(c[3])
        : "r"(a[0]), "r"(a[1]), "r"(a[2]), "r"(a[3]), "r"(b0), "r"(b1));
}
__device__ __forceinline__ void cpa16(uint32_t s, const void* g) {
    asm volatile("cp.async.cg.shared.global [%0], [%1], 16;"
                 :: "r"(s), "l"(g) : "memory");
}
#define CP_COMMIT() asm volatile("cp.async.commit_group;" ::: "memory")
#define CP_WAIT(n)  asm volatile("cp.async.wait_group %0;" :: "n"(n) : "memory")

// ---------------------------------------------------------------------------
// QKV projection: C = x @ W^T (bf16 HMMA, fp32 accum), C stored bf16.
// BM=128, BN=128, BK=64, 256 threads (warp grid 2m x 4n, warp tile 64x32).
// Smem rows: [row][64k] bf16 = 128B, 16B-chunk swizzle c ^= row&7.
// ---------------------------------------------------------------------------
__global__ __launch_bounds__(256, 1) void qkv_mma_kernel(
    const float* __restrict__ x,  const float* __restrict__ Wq,
    const float* __restrict__ Wk, const float* __restrict__ Wv)
{
    extern __shared__ char dynsm[];   // 2 x (As 16KB + Bs 16KB) = 64KB

    const float* W; __nv_bfloat16* C; float cs;
    if (blockIdx.z == 0)      { W = Wq; C = g_Q; cs = 0.015625f; }  // fold 1/sqrt(N)
    else if (blockIdx.z == 1) { W = Wk; C = g_K; cs = 1.0f; }
    else                      { W = Wv; C = g_V; cs = 1.0f; }

    const int m0 = blockIdx.y * 128, n0 = blockIdx.x * 128;
    const int tid = threadIdx.x, lane = tid & 31, wid = tid >> 5;
    const int wm = wid & 1, wn = wid >> 1;
    const int l7 = lane & 7, l15 = lane & 15, hi = lane >> 4;
    const uint32_t smb = su32(dynsm);

    // loader: thread -> (row = tid/2, k-half = (tid&1)*32)
    const int lrow = tid >> 1, kh = (tid & 1) * 32;
    const float* xs = x + (size_t)(m0 + lrow) * DM + kh;
    const float* ws = W + (size_t)(n0 + lrow) * DM + kh;

    uint32_t stoff[4];
#pragma unroll
    for (int i = 0; i < 4; i++) {
        int c = 4 * (tid & 1) + i;
        stoff[i] = (uint32_t)(lrow * 128 + ((c ^ (lrow & 7)) * 16));
    }

    float acc[4][4][4];
#pragma unroll
    for (int i = 0; i < 4; i++)
#pragma unroll
        for (int j = 0; j < 4; j++)
#pragma unroll
            for (int k = 0; k < 4; k++) acc[i][j][k] = 0.f;

    uint32_t pkA[16], pkB[16];
#pragma unroll
    for (int i = 0; i < 8; i++) {
        float4 a = *(const float4*)(xs + i * 4);
        float4 b = *(const float4*)(ws + i * 4);
        pkA[2*i] = packbf(a.x, a.y); pkA[2*i+1] = packbf(a.z, a.w);
        pkB[2*i] = packbf(b.x, b.y); pkB[2*i+1] = packbf(b.z, b.w);
    }

    for (int kc = 0; kc < 10; kc++) {
        char* bufA = dynsm + (kc & 1) * 32768;
        char* bufB = bufA + 16384;
        const uint32_t Asu = smb + (kc & 1) * 32768;
        const uint32_t Bsu = Asu + 16384;
#pragma unroll
        for (int i = 0; i < 4; i++) {
            *(uint4*)(bufA + stoff[i]) =
                make_uint4(pkA[4*i], pkA[4*i+1], pkA[4*i+2], pkA[4*i+3]);
            *(uint4*)(bufB + stoff[i]) =
                make_uint4(pkB[4*i], pkB[4*i+1], pkB[4*i+2], pkB[4*i+3]);
        }
        __syncthreads();

        if (kc < 9) {
            const float* xs2 = xs + (kc + 1) * 64;
            const float* ws2 = ws + (kc + 1) * 64;
#pragma unroll
            for (int i = 0; i < 8; i++) {
                float4 a = *(const float4*)(xs2 + i * 4);
                float4 b = *(const float4*)(ws2 + i * 4);
                pkA[2*i] = packbf(a.x, a.y); pkA[2*i+1] = packbf(a.z, a.w);
                pkB[2*i] = packbf(b.x, b.y); pkB[2*i+1] = packbf(b.z, b.w);
            }
        }

#pragma unroll
        for (int kk = 0; kk < 4; kk++) {
            uint32_t af[4][4];
#pragma unroll
            for (int mi = 0; mi < 4; mi++)
                ldsm4(af[mi], Asu + (uint32_t)((wm*64 + mi*16 + l15) * 128
                              + (((2*kk + hi) ^ l7) * 16)));
            uint32_t bf2[2][4];
#pragma unroll
            for (int bi = 0; bi < 2; bi++)
                ldsm4(bf2[bi], Bsu + (uint32_t)((wn*32 + bi*16 + hi*8 + l7) * 128
                               + (((2*kk + ((lane >> 3) & 1)) ^ l7) * 16)));
#pragma unroll
            for (int mi = 0; mi < 4; mi++) {
                mma16816(acc[mi][0], af[mi], bf2[0][0], bf2[0][1]);
                mma16816(acc[mi][1], af[mi], bf2[0][2], bf2[0][3]);
                mma16816(acc[mi][2], af[mi], bf2[1][0], bf2[1][1]);
                mma16816(acc[mi][3], af[mi], bf2[1][2], bf2[1][3]);
            }
        }
        __syncthreads();
    }

    // epilogue: pack fp32 -> bf16 pairs, store
    const int r = lane >> 2, q = lane & 3;
#pragma unroll
    for (int mi = 0; mi < 4; mi++) {
        int row0 = m0 + wm*64 + mi*16 + r;
#pragma unroll
        for (int ni = 0; ni < 4; ni++) {
            int col = n0 + wn*32 + ni*8 + 2*q;
            uint32_t p0 = packbf(acc[mi][ni][0]*cs, acc[mi][ni][1]*cs);
            uint32_t p1 = packbf(acc[mi][ni][2]*cs, acc[mi][ni][3]*cs);
            *(uint32_t*)&C[(size_t)row0 * DM + col] = p0;
            *(uint32_t*)&C[(size_t)(row0 + 8) * DM + col] = p1;
        }
    }
}

// ---------------------------------------------------------------------------
// Fused attention (flat-reshape head semantics), bf16 HMMA.
// Per CTA: one head x 128 Q rows. 8 warps, each owns a 16-row stripe.
// Ks smem [64 d][128 key] = K native layout; Vs [128 key][64 d] = V native.
// Both feed ldmatrix.trans B-frags directly; P repacked in registers.
// ---------------------------------------------------------------------------
__global__ __launch_bounds__(256, 1) void attn_mma_kernel()
{
    extern __shared__ char dynsm[];
    // Qs 16KB | Ks[2] 2x16KB | Vs[2] 2x16KB  -> 80KB
    const uint32_t smQ = su32(dynsm);
    const uint32_t smK = smQ + 16384;
    const uint32_t smV = smQ + 49152;

    const int h  = blockIdx.y;
    const int m0 = blockIdx.x * 128;
    const __nv_bfloat16* Qp = g_Q + (size_t)h * HS;
    const __nv_bfloat16* Kp = g_K + (size_t)h * HS;
    const __nv_bfloat16* Vp = g_V + (size_t)h * HS;
    float* Op = g_AO + (size_t)h * HS;

    const int tid = threadIdx.x, lane = tid & 31, wid = tid >> 5;
    const int l7 = lane & 7, l15 = lane & 15, hi = lane >> 4;

    uint32_t sw16[8];
#pragma unroll
    for (int j = 0; j < 8; j++) sw16[j] = (uint32_t)(((2*j + hi) ^ l7) * 16);

    // ---- prologue: async Q + tiles 0,1 ----
#pragma unroll
    for (int i = 0; i < 4; i++) {
        int idx = tid + 256 * i;
        int row = idx >> 3, c = idx & 7;
        cpa16(smQ + row*128 + ((c ^ (row & 7)) * 16),
              Qp + (size_t)(m0 + row) * DKH + c*8);
    }
    CP_COMMIT();

#define LOAD_TILE(TT, B) do {                                              \
    int nb = (TT) * 128;                                                   \
    _Pragma("unroll")                                                      \
    for (int i = 0; i < 4; i++) {                                          \
        int idx = tid + 256 * i;                                           \
        int row = idx >> 4, c = idx & 15;                                  \
        cpa16(smK + (B)*16384 + row*256 + ((c ^ (row & 7)) * 16),          \
              Kp + (size_t)row * NT + nb + c*8);                           \
    }                                                                      \
    _Pragma("unroll")                                                      \
    for (int i = 0; i < 4; i++) {                                          \
        int idx = tid + 256 * i;                                           \
        int row = idx >> 3, c = idx & 7;                                   \
        cpa16(smV + (B)*16384 + row*128 + ((c ^ (row & 7)) * 16),          \
              Vp + (size_t)(nb + row) * DKH + c*8);                        \
    }                                                                      \
} while (0)

    LOAD_TILE(0, 0); CP_COMMIT();
    LOAD_TILE(1, 1); CP_COMMIT();
    CP_WAIT(1);            // Q + tile0 ready
    __syncthreads();

    // Q fragments (persistent)
    uint32_t qa[4][4];
#pragma unroll
    for (int kk = 0; kk < 4; kk++)
        ldsm4(qa[kk], smQ + (uint32_t)((16*wid + l15) * 128) + sw16[kk]);

    float oc[8][4];
#pragma unroll
    for (int j = 0; j < 8; j++)
#pragma unroll
        for (int k = 0; k < 4; k++) oc[j][k] = 0.f;
    float ls0 = 0.f, ls1 = 0.f;

    for (int t = 0; t < 32; t++) {
        const uint32_t Ksu = smK + (uint32_t)(t & 1) * 16384;
        const uint32_t Vsu = smV + (uint32_t)(t & 1) * 16384;

        // ---- MMA1: S[16,128] = Q @ K' ----
        float sc[16][4];
#pragma unroll
        for (int j = 0; j < 16; j++)
#pragma unroll
            for (int k = 0; k < 4; k++) sc[j][k] = 0.f;

#pragma unroll
        for (int kk = 0; kk < 4; kk++) {
#pragma unroll
            for (int jj = 0; jj < 8; jj++) {
                uint32_t bb[4];
                ldsm4t(bb, Ksu + (uint32_t)(kk*4096 + l15*256) + sw16[jj]);
                mma16816(sc[2*jj],     qa[kk], bb[0], bb[1]);
                mma16816(sc[2*jj + 1], qa[kk], bb[2], bb[3]);
            }
        }

        // ---- exp + register repack to P A-frags + rowsum ----
        uint32_t pa[8][4];
#pragma unroll
        for (int jj = 0; jj < 8; jj++) {
            float e00 = __expf(sc[2*jj][0]),   e01 = __expf(sc[2*jj][1]);
            float e02 = __expf(sc[2*jj][2]),   e03 = __expf(sc[2*jj][3]);
            float e10 = __expf(sc[2*jj+1][0]), e11 = __expf(sc[2*jj+1][1]);
            float e12 = __expf(sc[2*jj+1][2]), e13 = __expf(sc[2*jj+1][3]);
            ls0 += (e00 + e01) + (e10 + e11);
            ls1 += (e02 + e03) + (e12 + e13);
            pa[jj][0] = packbf(e00, e01);
            pa[jj][1] = packbf(e02, e03);
            pa[jj][2] = packbf(e10, e11);
            pa[jj][3] = packbf(e12, e13);
        }

        // ---- MMA2: O[16,64] += P @ V ----
#pragma unroll
        for (int kk = 0; kk < 8; kk++) {
#pragma unroll
            for (int jj = 0; jj < 4; jj++) {
                uint32_t bb[4];
                ldsm4t(bb, Vsu + (uint32_t)(kk*2048 + l15*128) + sw16[jj]);
                mma16816(oc[2*jj],     pa[kk], bb[0], bb[1]);
                mma16816(oc[2*jj + 1], pa[kk], bb[2], bb[3]);
            }
        }

        __syncthreads();   // all readers done before overwriting buf (t&1)
        if (t + 2 < 32) {
            LOAD_TILE(t + 2, t & 1);
            CP_COMMIT();
            CP_WAIT(1);    // tile t+1 guaranteed complete
        } else {
            CP_WAIT(0);
        }
        __syncthreads();
    }
#undef LOAD_TILE

    // rowsum reduce across the quad (lanes sharing a row)
    ls0 += __shfl_xor_sync(0xffffffffu, ls0, 1);
    ls0 += __shfl_xor_sync(0xffffffffu, ls0, 2);
    ls1 += __shfl_xor_sync(0xffffffffu, ls1, 1);
    ls1 += __shfl_xor_sync(0xffffffffu, ls1, 2);
    const float inv0 = 1.0f / ls0, inv1 = 1.0f / ls1;

    const int r = lane >> 2, q = lane & 3;
    const int row0 = m0 + 16*wid + r;
#pragma unroll
    for (int j = 0; j < 8; j++) {
        int d = 8*j + 2*q;
        *(float2*)(Op + (size_t)row0 * DKH + d) =
            make_float2(oc[j][0] * inv0, oc[j][1] * inv0);
        *(float2*)(Op + (size_t)(row0 + 8) * DKH + d) =
            make_float2(oc[j][2] * inv1, oc[j][3] * inv1);
    }
}

// ---------------------------------------------------------------------------
// Residual add + LayerNorm (biased variance, eps=1e-5), one CTA per row
// ---------------------------------------------------------------------------
__global__ __launch_bounds__(256) void ln_kernel(
    const float* __restrict__ x,
    const float* __restrict__ gamma,
    const float* __restrict__ beta,
    float* __restrict__ out)
{
    const int row = blockIdx.x;
    const int tid = threadIdx.x;
    const float* ao = g_AO + (size_t)row * DM;
    const float* xr = x    + (size_t)row * DM;

    float v[3];
    float sum = 0.f, ss = 0.f;
    int k = 0;
    for (int i = tid; i < DM; i += 256, k++) {
        float val = ao[i] + xr[i];
        v[k] = val;
        sum += val;
        ss  += val * val;
    }

#pragma unroll
    for (int off = 16; off > 0; off >>= 1) {
        sum += __shfl_xor_sync(0xffffffffu, sum, off);
        ss  += __shfl_xor_sync(0xffffffffu, ss,  off);
    }
    __shared__ float s1[8], s2[8];
    const int w = tid >> 5, lane = tid & 31;
    if (lane == 0) { s1[w] = sum; s2[w] = ss; }
    __syncthreads();
    if (w == 0) {
        sum = s1[lane & 7];
        ss  = s2[lane & 7];
#pragma unroll
        for (int off = 4; off > 0; off >>= 1) {
            sum += __shfl_xor_sync(0xffffffffu, sum, off);
            ss  += __shfl_xor_sync(0xffffffffu, ss,  off);
        }
        if (lane == 0) { s1[0] = sum; s2[0] = ss; }
    }
    __syncthreads();
    sum = s1[0]; ss = s2[0];

    const float mean = sum * (1.0f / DM);
    const float var  = ss * (1.0f / DM) - mean * mean;
    const float rstd = rsqrtf(var + 1e-5f);

    k = 0;
    for (int i = tid; i < DM; i += 256, k++) {
        out[(size_t)row * DM + i] = (v[k] - mean) * rstd * gamma[i] + beta[i];
    }
}

// ---------------------------------------------------------------------------
extern "C" void kernel_launch(void* const* d_in, const int* in_sizes, int n_in,
                              void* d_out, int out_size)
{
    const float* x     = (const float*)d_in[0];
    const float* Wq    = (const float*)d_in[1];
    const float* Wk    = (const float*)d_in[2];
    const float* Wv    = (const float*)d_in[3];
    const float* gamma = (const float*)d_in[4];
    const float* beta  = (const float*)d_in[5];
    float* out = (float*)d_out;

    const int qkv_smem  = 65536;   // 2 x (16KB A + 16KB B)
    const int attn_smem = 81920;   // Qs 16KB + Ks 2x16KB + Vs 2x16KB
    cudaFuncSetAttribute(qkv_mma_kernel,
                         cudaFuncAttributeMaxDynamicSharedMemorySize, qkv_smem);
    cudaFuncSetAttribute(attn_mma_kernel,
                         cudaFuncAttributeMaxDynamicSharedMemorySize, attn_smem);

    qkv_mma_kernel<<<dim3(DM / 128, NT / 128, 3), 256, qkv_smem>>>(x, Wq, Wk, Wv);
    attn_mma_kernel<<<dim3(NT / 128, NH), 256, attn_smem>>>();
    ln_kernel<<<NT, 256>>>(x, gamma, beta, out);
}

// round 14
// speedup vs baseline: 1.0013x; 1.0013x over previous
#include <cuda_runtime.h>
#include <cuda_bf16.h>
#include <cstdint>

#define NT  4096
#define DM  640
#define NH  10
#define DKH 64
#define HS  (NT * DKH)

// Scratch (allocation-free rule: __device__ globals). Q/K/V stored bf16.
__device__ __nv_bfloat16 g_Q[NT * DM];
__device__ __nv_bfloat16 g_K[NT * DM];
__device__ __nv_bfloat16 g_V[NT * DM];
__device__ float g_AO[NT * DM];

// ---------------------------------------------------------------------------
// Helpers (arch-neutral PTX: sm_80-era, accepted by target sm_103)
// ---------------------------------------------------------------------------
__device__ __forceinline__ uint32_t su32(const void* p) {
    uint32_t a;
    asm("{ .reg .u64 t; cvta.to.shared.u64 t, %1; cvt.u32.u64 %0, t; }"
        : "=r"(a) : "l"(p));
    return a;
}
// pack two f32 -> bf16x2 (lo = first arg)
__device__ __forceinline__ uint32_t packbf(float lo, float hi) {
    uint32_t r;
    asm("cvt.rn.bf16x2.f32 %0, %1, %2;" : "=r"(r) : "f"(hi), "f"(lo));
    return r;
}
__device__ __forceinline__ void ldsm4(uint32_t r[4], uint32_t a) {
    asm volatile("ldmatrix.sync.aligned.m8n8.x4.shared.b16 {%0,%1,%2,%3}, [%4];"
        : "=r"(r[0]), "=r"(r[1]), "=r"(r[2]), "=r"(r[3]) : "r"(a));
}
__device__ __forceinline__ void ldsm4t(uint32_t r[4], uint32_t a) {
    asm volatile("ldmatrix.sync.aligned.m8n8.x4.trans.shared.b16 {%0,%1,%2,%3}, [%4];"
        : "=r"(r[0]), "=r"(r[1]), "=r"(r[2]), "=r"(r[3]) : "r"(a));
}
__device__ __forceinline__ void mma16816(float* c, const uint32_t* a,
                                         uint32_t b0, uint32_t b1) {
    asm volatile("mma.sync.aligned.m16n8k16.row.col.f32.bf16.bf16.f32 "
        "{%0,%1,%2,%3}, {%4,%5,%6,%7}, {%8,%9}, {%0,%1,%2,%3};"
        : "+f"(c[0]), "+f"(c[1]), "+f"(c[2]), "+f"(c[3])
        : "r"(a[0]), "r"(a[1]), "r"(a[2]), "r"(a[3]), "r"(b0), "r"(b1));
}
__device__ __forceinline__ void cpa16(uint32_t s, const void* g) {
    asm volatile("cp.async.cg.shared.global [%0], [%1], 16;"
                 :: "r"(s), "l"(g) : "memory");
}
#define CP_COMMIT() asm volatile("cp.async.commit_group;" ::: "memory")
#define CP_WAIT(n)  asm volatile("cp.async.wait_group %0;" :: "n"(n) : "memory")

// ---------------------------------------------------------------------------
// QKV projection: C = x @ W^T (bf16 HMMA, fp32 accum), C stored bf16.
// BM=128, BN=128, BK=64, 256 threads (warp grid 2m x 4n, warp tile 64x32).
// Smem rows: [row][64k] bf16 = 128B, 16B-chunk swizzle c ^= row&7.
// ---------------------------------------------------------------------------
__global__ __launch_bounds__(256, 1) void qkv_mma_kernel(
    const float* __restrict__ x,  const float* __restrict__ Wq,
    const float* __restrict__ Wk, const float* __restrict__ Wv)
{
    extern __shared__ char dynsm[];   // 2 x (As 16KB + Bs 16KB) = 64KB

    const float* W; __nv_bfloat16* C; float cs;
    if (blockIdx.z == 0)      { W = Wq; C = g_Q; cs = 0.015625f; }  // fold 1/sqrt(N)
    else if (blockIdx.z == 1) { W = Wk; C = g_K; cs = 1.0f; }
    else                      { W = Wv; C = g_V; cs = 1.0f; }

    const int m0 = blockIdx.y * 128, n0 = blockIdx.x * 128;
    const int tid = threadIdx.x, lane = tid & 31, wid = tid >> 5;
    const int wm = wid & 1, wn = wid >> 1;
    const int l7 = lane & 7, l15 = lane & 15, hi = lane >> 4;
    const uint32_t smb = su32(dynsm);

    // loader: thread -> (row = tid/2, k-half = (tid&1)*32)
    const int lrow = tid >> 1, kh = (tid & 1) * 32;
    const float* xs = x + (size_t)(m0 + lrow) * DM + kh;
    const float* ws = W + (size_t)(n0 + lrow) * DM + kh;

    uint32_t stoff[4];
#pragma unroll
    for (int i = 0; i < 4; i++) {
        int c = 4 * (tid & 1) + i;
        stoff[i] = (uint32_t)(lrow * 128 + ((c ^ (lrow & 7)) * 16));
    }

    float acc[4][4][4];
#pragma unroll
    for (int i = 0; i < 4; i++)
#pragma unroll
        for (int j = 0; j < 4; j++)
#pragma unroll
            for (int k = 0; k < 4; k++) acc[i][j][k] = 0.f;

    uint32_t pkA[16], pkB[16];
#pragma unroll
    for (int i = 0; i < 8; i++) {
        float4 a = *(const float4*)(xs + i * 4);
        float4 b = *(const float4*)(ws + i * 4);
        pkA[2*i] = packbf(a.x, a.y); pkA[2*i+1] = packbf(a.z, a.w);
        pkB[2*i] = packbf(b.x, b.y); pkB[2*i+1] = packbf(b.z, b.w);
    }

    for (int kc = 0; kc < 10; kc++) {
        char* bufA = dynsm + (kc & 1) * 32768;
        char* bufB = bufA + 16384;
        const uint32_t Asu = smb + (kc & 1) * 32768;
        const uint32_t Bsu = Asu + 16384;
#pragma unroll
        for (int i = 0; i < 4; i++) {
            *(uint4*)(bufA + stoff[i]) =
                make_uint4(pkA[4*i], pkA[4*i+1], pkA[4*i+2], pkA[4*i+3]);
            *(uint4*)(bufB + stoff[i]) =
                make_uint4(pkB[4*i], pkB[4*i+1], pkB[4*i+2], pkB[4*i+3]);
        }
        __syncthreads();

        if (kc < 9) {
            const float* xs2 = xs + (kc + 1) * 64;
            const float* ws2 = ws + (kc + 1) * 64;
#pragma unroll
            for (int i = 0; i < 8; i++) {
                float4 a = *(const float4*)(xs2 + i * 4);
                float4 b = *(const float4*)(ws2 + i * 4);
                pkA[2*i] = packbf(a.x, a.y); pkA[2*i+1] = packbf(a.z, a.w);
                pkB[2*i] = packbf(b.x, b.y); pkB[2*i+1] = packbf(b.z, b.w);
            }
        }

#pragma unroll
        for (int kk = 0; kk < 4; kk++) {
            uint32_t af[4][4];
#pragma unroll
            for (int mi = 0; mi < 4; mi++)
                ldsm4(af[mi], Asu + (uint32_t)((wm*64 + mi*16 + l15) * 128
                              + (((2*kk + hi) ^ l7) * 16)));
            uint32_t bf2[2][4];
#pragma unroll
            for (int bi = 0; bi < 2; bi++)
                ldsm4(bf2[bi], Bsu + (uint32_t)((wn*32 + bi*16 + hi*8 + l7) * 128
                               + (((2*kk + ((lane >> 3) & 1)) ^ l7) * 16)));
#pragma unroll
            for (int mi = 0; mi < 4; mi++) {
                mma16816(acc[mi][0], af[mi], bf2[0][0], bf2[0][1]);
                mma16816(acc[mi][1], af[mi], bf2[0][2], bf2[0][3]);
                mma16816(acc[mi][2], af[mi], bf2[1][0], bf2[1][1]);
                mma16816(acc[mi][3], af[mi], bf2[1][2], bf2[1][3]);
            }
        }
        __syncthreads();
    }

    // epilogue: pack fp32 -> bf16 pairs, store
    const int r = lane >> 2, q = lane & 3;
#pragma unroll
    for (int mi = 0; mi < 4; mi++) {
        int row0 = m0 + wm*64 + mi*16 + r;
#pragma unroll
        for (int ni = 0; ni < 4; ni++) {
            int col = n0 + wn*32 + ni*8 + 2*q;
            uint32_t p0 = packbf(acc[mi][ni][0]*cs, acc[mi][ni][1]*cs);
            uint32_t p1 = packbf(acc[mi][ni][2]*cs, acc[mi][ni][3]*cs);
            *(uint32_t*)&C[(size_t)row0 * DM + col] = p0;
            *(uint32_t*)&C[(size_t)(row0 + 8) * DM + col] = p1;
        }
    }
}

// ---------------------------------------------------------------------------
// Fused attention (flat-reshape head semantics), bf16 HMMA.
// Per CTA: one head x 128 Q rows. 8 warps, each owns a 16-row stripe.
// Ks smem [64 d][128 key] = K native layout; Vs [128 key][64 d] = V native.
// Both feed ldmatrix.trans B-frags directly; P repacked in registers.
// ---------------------------------------------------------------------------
__global__ __launch_bounds__(256, 1) void attn_mma_kernel()
{
    extern __shared__ char dynsm[];
    // Qs 16KB | Ks[2] 2x16KB | Vs[2] 2x16KB  -> 80KB
    const uint32_t smQ = su32(dynsm);
    const uint32_t smK = smQ + 16384;
    const uint32_t smV = smQ + 49152;

    const int h  = blockIdx.y;
    const int m0 = blockIdx.x * 128;
    const __nv_bfloat16* Qp = g_Q + (size_t)h * HS;
    const __nv_bfloat16* Kp = g_K + (size_t)h * HS;
    const __nv_bfloat16* Vp = g_V + (size_t)h * HS;
    float* Op = g_AO + (size_t)h * HS;

    const int tid = threadIdx.x, lane = tid & 31, wid = tid >> 5;
    const int l7 = lane & 7, l15 = lane & 15, hi = lane >> 4;

    uint32_t sw16[8];
#pragma unroll
    for (int j = 0; j < 8; j++) sw16[j] = (uint32_t)(((2*j + hi) ^ l7) * 16);

    // ---- prologue: async Q + tiles 0,1 ----
#pragma unroll
    for (int i = 0; i < 4; i++) {
        int idx = tid + 256 * i;
        int row = idx >> 3, c = idx & 7;
        cpa16(smQ + row*128 + ((c ^ (row & 7)) * 16),
              Qp + (size_t)(m0 + row) * DKH + c*8);
    }
    CP_COMMIT();

#define LOAD_TILE(TT, B) do {                                              \
    int nb = (TT) * 128;                                                   \
    _Pragma("unroll")                                                      \
    for (int i = 0; i < 4; i++) {                                          \
        int idx = tid + 256 * i;                                           \
        int row = idx >> 4, c = idx & 15;                                  \
        cpa16(smK + (B)*16384 + row*256 + ((c ^ (row & 7)) * 16),          \
              Kp + (size_t)row * NT + nb + c*8);                           \
    }                                                                      \
    _Pragma("unroll")                                                      \
    for (int i = 0; i < 4; i++) {                                          \
        int idx = tid + 256 * i;                                           \
        int row = idx >> 3, c = idx & 7;                                   \
        cpa16(smV + (B)*16384 + row*128 + ((c ^ (row & 7)) * 16),          \
              Vp + (size_t)(nb + row) * DKH + c*8);                        \
    }                                                                      \
} while (0)

    LOAD_TILE(0, 0); CP_COMMIT();
    LOAD_TILE(1, 1); CP_COMMIT();
    CP_WAIT(1);            // Q + tile0 ready
    __syncthreads();

    // Q fragments (persistent)
    uint32_t qa[4][4];
#pragma unroll
    for (int kk = 0; kk < 4; kk++)
        ldsm4(qa[kk], smQ + (uint32_t)((16*wid + l15) * 128) + sw16[kk]);

    float oc[8][4];
#pragma unroll
    for (int j = 0; j < 8; j++)
#pragma unroll
        for (int k = 0; k < 4; k++) oc[j][k] = 0.f;
    float ls0 = 0.f, ls1 = 0.f;

    for (int t = 0; t < 32; t++) {
        const uint32_t Ksu = smK + (uint32_t)(t & 1) * 16384;
        const uint32_t Vsu = smV + (uint32_t)(t & 1) * 16384;

        // ---- MMA1: S[16,128] = Q @ K' ----
        float sc[16][4];
#pragma unroll
        for (int j = 0; j < 16; j++)
#pragma unroll
            for (int k = 0; k < 4; k++) sc[j][k] = 0.f;

#pragma unroll
        for (int kk = 0; kk < 4; kk++) {
#pragma unroll
            for (int jj = 0; jj < 8; jj++) {
                uint32_t bb[4];
                ldsm4t(bb, Ksu + (uint32_t)(kk*4096 + l15*256) + sw16[jj]);
                mma16816(sc[2*jj],     qa[kk], bb[0], bb[1]);
                mma16816(sc[2*jj + 1], qa[kk], bb[2], bb[3]);
            }
        }

        // ---- exp + register repack to P A-frags + rowsum ----
        uint32_t pa[8][4];
#pragma unroll
        for (int jj = 0; jj < 8; jj++) {
            float e00 = __expf(sc[2*jj][0]),   e01 = __expf(sc[2*jj][1]);
            float e02 = __expf(sc[2*jj][2]),   e03 = __expf(sc[2*jj][3]);
            float e10 = __expf(sc[2*jj+1][0]), e11 = __expf(sc[2*jj+1][1]);
            float e12 = __expf(sc[2*jj+1][2]), e13 = __expf(sc[2*jj+1][3]);
            ls0 += (e00 + e01) + (e10 + e11);
            ls1 += (e02 + e03) + (e12 + e13);
            pa[jj][0] = packbf(e00, e01);
            pa[jj][1] = packbf(e02, e03);
            pa[jj][2] = packbf(e10, e11);
            pa[jj][3] = packbf(e12, e13);
        }

        // ---- MMA2: O[16,64] += P @ V ----
#pragma unroll
        for (int kk = 0; kk < 8; kk++) {
#pragma unroll
            for (int jj = 0; jj < 4; jj++) {
                uint32_t bb[4];
                ldsm4t(bb, Vsu + (uint32_t)(kk*2048 + l15*128) + sw16[jj]);
                mma16816(oc[2*jj],     pa[kk], bb[0], bb[1]);
                mma16816(oc[2*jj + 1], pa[kk], bb[2], bb[3]);
            }
        }

        __syncthreads();   // all readers done before overwriting buf (t&1)
        if (t + 2 < 32) {
            LOAD_TILE(t + 2, t & 1);
            CP_COMMIT();
            CP_WAIT(1);    // tile t+1 guaranteed complete
        } else {
            CP_WAIT(0);
        }
        __syncthreads();
    }
#undef LOAD_TILE

    // rowsum reduce across the quad (lanes sharing a row)
    ls0 += __shfl_xor_sync(0xffffffffu, ls0, 1);
    ls0 += __shfl_xor_sync(0xffffffffu, ls0, 2);
    ls1 += __shfl_xor_sync(0xffffffffu, ls1, 1);
    ls1 += __shfl_xor_sync(0xffffffffu, ls1, 2);
    const float inv0 = 1.0f / ls0, inv1 = 1.0f / ls1;

    const int r = lane >> 2, q = lane & 3;
    const int row0 = m0 + 16*wid + r;
#pragma unroll
    for (int j = 0; j < 8; j++) {
        int d = 8*j + 2*q;
        *(float2*)(Op + (size_t)row0 * DKH + d) =
            make_float2(oc[j][0] * inv0, oc[j][1] * inv0);
        *(float2*)(Op + (size_t)(row0 + 8) * DKH + d) =
            make_float2(oc[j][2] * inv1, oc[j][3] * inv1);
    }
}

// ---------------------------------------------------------------------------
// Residual add + LayerNorm (biased variance, eps=1e-5), one CTA per row
// ---------------------------------------------------------------------------
__global__ __launch_bounds__(256) void ln_kernel(
    const float* __restrict__ x,
    const float* __restrict__ gamma,
    const float* __restrict__ beta,
    float* __restrict__ out)
{
    const int row = blockIdx.x;
    const int tid = threadIdx.x;
    const float* ao = g_AO + (size_t)row * DM;
    const float* xr = x    + (size_t)row * DM;

    float v[3];
    float sum = 0.f, ss = 0.f;
    int k = 0;
    for (int i = tid; i < DM; i += 256, k++) {
        float val = ao[i] + xr[i];
        v[k] = val;
        sum += val;
        ss  += val * val;
    }

#pragma unroll
    for (int off = 16; off > 0; off >>= 1) {
        sum += __shfl_xor_sync(0xffffffffu, sum, off);
        ss  += __shfl_xor_sync(0xffffffffu, ss,  off);
    }
    __shared__ float s1[8], s2[8];
    const int w = tid >> 5, lane = tid & 31;
    if (lane == 0) { s1[w] = sum; s2[w] = ss; }
    __syncthreads();
    if (w == 0) {
        sum = s1[lane & 7];
        ss  = s2[lane & 7];
#pragma unroll
        for (int off = 4; off > 0; off >>= 1) {
            sum += __shfl_xor_sync(0xffffffffu, sum, off);
            ss  += __shfl_xor_sync(0xffffffffu, ss,  off);
        }
        if (lane == 0) { s1[0] = sum; s2[0] = ss; }
    }
    __syncthreads();
    sum = s1[0]; ss = s2[0];

    const float mean = sum * (1.0f / DM);
    const float var  = ss * (1.0f / DM) - mean * mean;
    const float rstd = rsqrtf(var + 1e-5f);

    k = 0;
    for (int i = tid; i < DM; i += 256, k++) {
        out[(size_t)row * DM + i] = (v[k] - mean) * rstd * gamma[i] + beta[i];
    }
}

// ---------------------------------------------------------------------------
extern "C" void kernel_launch(void* const* d_in, const int* in_sizes, int n_in,
                              void* d_out, int out_size)
{
    const float* x     = (const float*)d_in[0];
    const float* Wq    = (const float*)d_in[1];
    const float* Wk    = (const float*)d_in[2];
    const float* Wv    = (const float*)d_in[3];
    const float* gamma = (const float*)d_in[4];
    const float* beta  = (const float*)d_in[5];
    float* out = (float*)d_out;

    const int qkv_smem  = 65536;   // 2 x (16KB A + 16KB B)
    const int attn_smem = 81920;   // Qs 16KB + Ks 2x16KB + Vs 2x16KB
    cudaFuncSetAttribute(qkv_mma_kernel,
                         cudaFuncAttributeMaxDynamicSharedMemorySize, qkv_smem);
    cudaFuncSetAttribute(attn_mma_kernel,
                         cudaFuncAttributeMaxDynamicSharedMemorySize, attn_smem);

    qkv_mma_kernel<<<dim3(DM / 128, NT / 128, 3), 256, qkv_smem>>>(x, Wq, Wk, Wv);
    attn_mma_kernel<<<dim3(NT / 128, NH), 256, attn_smem>>>();
    ln_kernel<<<NT, 256>>>(x, gamma, beta, out);
}